// round 5
// baseline (speedup 1.0000x reference)
#include <cuda_runtime.h>
#include <cuda_bf16.h>
#include <math.h>
#include <stdint.h>

// ---------------- problem constants ----------------
#define BB   4
#define NN   1024
#define KNB  32
#define CS   384
#define CZ   128
#define CH   16
#define HH   12
#define PQn  4
#define PVn  8
#define NODES (BB*NN)        // 4096
#define PROJ  1152           // q(192)+k(192)+v(192)+qpts(144)+kvpts(432)
#define EDGES (NODES*KNB)    // 131072
#define EOC   44             // b_bias(12) + pair(32)
#define CVC   960            // o(192)+o_pt(288)+dists(96)+o_pair(384)
#define COUT  384

// ---------------- scratch (device globals; no allocation) ----------------
__device__ float g_wcat[CS*PROJ];
__device__ float g_proj[NODES*PROJ];
__device__ float g_stat[NODES*2];
__device__ float g_zstat[EDGES*2];
__device__ float g_wz  [CZ*EOC];
__device__ float g_eo  [EDGES*EOC];
__device__ float g_cvec[NODES*CVC];

// ---------------- helpers ----------------
__device__ __forceinline__ uint32_t smem_u32(const void* p) {
    uint32_t a;
    asm("{ .reg .u64 t; cvta.to.shared.u64 t, %1; cvt.u32.u64 %0, t; }"
        : "=r"(a) : "l"(p));
    return a;
}
__device__ __forceinline__ void cvt_hilo(float x, __nv_bfloat16& h, __nv_bfloat16& l) {
    h = __float2bfloat16(x);
    l = __float2bfloat16(x - __bfloat162float(h));
}
__device__ __forceinline__ void ldsm4(uint32_t& r0, uint32_t& r1, uint32_t& r2,
                                      uint32_t& r3, uint32_t addr) {
    asm volatile("ldmatrix.sync.aligned.m8n8.x4.shared.b16 {%0,%1,%2,%3}, [%4];"
                 : "=r"(r0), "=r"(r1), "=r"(r2), "=r"(r3) : "r"(addr));
}
__device__ __forceinline__ void ldsm4t(uint32_t& r0, uint32_t& r1, uint32_t& r2,
                                       uint32_t& r3, uint32_t addr) {
    asm volatile("ldmatrix.sync.aligned.m8n8.x4.trans.shared.b16 {%0,%1,%2,%3}, [%4];"
                 : "=r"(r0), "=r"(r1), "=r"(r2), "=r"(r3) : "r"(addr));
}
__device__ __forceinline__ void mma16816(float* c, const uint32_t* a, const uint32_t* b) {
    asm volatile(
        "mma.sync.aligned.m16n8k16.row.col.f32.bf16.bf16.f32 "
        "{%0,%1,%2,%3}, {%4,%5,%6,%7}, {%8,%9}, {%0,%1,%2,%3};"
        : "+f"(c[0]), "+f"(c[1]), "+f"(c[2]), "+f"(c[3])
        : "r"(a[0]), "r"(a[1]), "r"(a[2]), "r"(a[3]), "r"(b[0]), "r"(b[1]));
}

// ================= weight packing ==========================
__global__ void pack_wcat(const float* __restrict__ wq, const float* __restrict__ wk,
                          const float* __restrict__ wv, const float* __restrict__ wqp,
                          const float* __restrict__ wkv) {
    int idx = blockIdx.x * 256 + threadIdx.x;
    if (idx >= CS * PROJ) return;
    int i = idx / PROJ, j = idx % PROJ;
    float v;
    if      (j < 192) v = wq [i*192 + j];
    else if (j < 384) v = wk [i*192 + j - 192];
    else if (j < 576) v = wv [i*192 + j - 384];
    else if (j < 720) v = wqp[i*144 + j - 576];
    else              v = wkv[i*432 + j - 720];
    g_wcat[idx] = v;
}

__global__ void pack_wz(const float* __restrict__ wb, const float* __restrict__ wdz) {
    int idx = blockIdx.x * 256 + threadIdx.x;
    if (idx >= CZ * EOC) return;
    int i = idx / EOC, j = idx % EOC;
    g_wz[idx] = (j < 12) ? wb[i*12 + j] : wdz[i*32 + j - 12];
}

// ---------------- s row stats (warp per node) ----------------
__global__ __launch_bounds__(256) void k_stat_s(const float* __restrict__ s) {
    int node = blockIdx.x * 8 + (threadIdx.x >> 5);
    int lane = threadIdx.x & 31;
    const float* x = s + (size_t)node * CS;
    float sum = 0.f, ssq = 0.f;
    #pragma unroll
    for (int i = 0; i < 3; i++) {
        float4 v = *(const float4*)(x + lane * 4 + i * 128);
        sum += v.x + v.y + v.z + v.w;
        ssq += v.x*v.x + v.y*v.y + v.z*v.z + v.w*v.w;
    }
    #pragma unroll
    for (int o = 16; o; o >>= 1) {
        sum += __shfl_xor_sync(0xffffffffu, sum, o);
        ssq += __shfl_xor_sync(0xffffffffu, ssq, o);
    }
    if (lane == 0) {
        float mean = sum * (1.0f / CS);
        float var  = ssq * (1.0f / CS) - mean * mean;
        g_stat[node*2    ] = mean;
        g_stat[node*2 + 1] = rsqrtf(var + 1e-5f);
    }
}

// ================= bf16x3 tensor-core GEMM via mma.sync ====================
// Software pipelined: next chunk's global loads issued before MMA passes.
// CTA tile BM x 128, 8 warps (2 M x 4 N), warp tile (BM/2) x 32.
#define AST 40
#define BST 136

template<int BM, bool LN>
__global__ __launch_bounds__(256) void tgemm(const float* __restrict__ A,
                                             const float* __restrict__ B,
                                             float* __restrict__ C,
                                             int Kd, int Nd, int nk,
                                             const float* __restrict__ stat,
                                             const float* __restrict__ gam,
                                             const float* __restrict__ bet) {
    constexpr int MT  = BM / 32;          // m16 fragments per warp
    constexpr int AL4 = BM / 32;          // float4 A-loads per thread
    __shared__ __nv_bfloat16 Ah[BM * AST];
    __shared__ __nv_bfloat16 Al[BM * AST];
    __shared__ __nv_bfloat16 Bh[32 * BST];
    __shared__ __nv_bfloat16 Bl[32 * BST];

    int tid = threadIdx.x, wid = tid >> 5, lane = tid & 31;
    int m0 = blockIdx.x * BM, n0 = blockIdx.y * 128;
    int wm = (wid >> 2) * (BM / 2);
    int wn = (wid & 3) * 32;

    float acc[MT][4][4];
    #pragma unroll
    for (int i = 0; i < MT; i++)
        #pragma unroll
        for (int j = 0; j < 4; j++)
            #pragma unroll
            for (int r = 0; r < 4; r++) acc[i][j][r] = 0.f;

    uint32_t ah_base = smem_u32(Ah), al_base = smem_u32(Al);
    uint32_t bh_base = smem_u32(Bh), bl_base = smem_u32(Bl);

    int a_row = wm + (lane & 15);
    int a_col = (lane >> 4) << 3;
    int b_row = (lane & 7) + ((lane >> 3) & 1) * 8;
    int b_col = wn + ((lane >> 4) << 3);

    float4 ar[AL4], br[4];

    auto loadA = [&](int c) {
        int k0 = c * 32;
        #pragma unroll
        for (int t = 0; t < AL4; t++) {
            int f4 = tid + t * 256;
            int row = f4 >> 3, col = (f4 & 7) * 4;
            float4 v = *(const float4*)(A + (size_t)(m0 + row) * Kd + k0 + col);
            if (LN) {
                float mean = stat[(m0 + row) * 2];
                float rstd = stat[(m0 + row) * 2 + 1];
                v.x = (v.x - mean) * rstd * __ldg(gam + k0 + col + 0) + __ldg(bet + k0 + col + 0);
                v.y = (v.y - mean) * rstd * __ldg(gam + k0 + col + 1) + __ldg(bet + k0 + col + 1);
                v.z = (v.z - mean) * rstd * __ldg(gam + k0 + col + 2) + __ldg(bet + k0 + col + 2);
                v.w = (v.w - mean) * rstd * __ldg(gam + k0 + col + 3) + __ldg(bet + k0 + col + 3);
            }
            ar[t] = v;
        }
    };
    auto loadB = [&](int c) {
        int k0 = c * 32;
        #pragma unroll
        for (int t = 0; t < 4; t++) {
            int f4 = tid + t * 256;
            int kr = f4 >> 5, nn = (f4 & 31) * 4;
            br[t] = *(const float4*)(B + (size_t)(k0 + kr) * Nd + n0 + nn);
        }
    };
    auto storeAB = [&]() {
        #pragma unroll
        for (int t = 0; t < AL4; t++) {
            int f4 = tid + t * 256;
            int row = f4 >> 3, col = (f4 & 7) * 4;
            __nv_bfloat16 h0,h1,h2,h3,l0,l1,l2,l3;
            cvt_hilo(ar[t].x,h0,l0); cvt_hilo(ar[t].y,h1,l1);
            cvt_hilo(ar[t].z,h2,l2); cvt_hilo(ar[t].w,h3,l3);
            *(__nv_bfloat162*)&Ah[row*AST + col    ] = __nv_bfloat162(h0,h1);
            *(__nv_bfloat162*)&Ah[row*AST + col + 2] = __nv_bfloat162(h2,h3);
            *(__nv_bfloat162*)&Al[row*AST + col    ] = __nv_bfloat162(l0,l1);
            *(__nv_bfloat162*)&Al[row*AST + col + 2] = __nv_bfloat162(l2,l3);
        }
        #pragma unroll
        for (int t = 0; t < 4; t++) {
            int f4 = tid + t * 256;
            int kr = f4 >> 5, nn = (f4 & 31) * 4;
            __nv_bfloat16 h0,h1,h2,h3,l0,l1,l2,l3;
            cvt_hilo(br[t].x,h0,l0); cvt_hilo(br[t].y,h1,l1);
            cvt_hilo(br[t].z,h2,l2); cvt_hilo(br[t].w,h3,l3);
            *(__nv_bfloat162*)&Bh[kr*BST + nn    ] = __nv_bfloat162(h0,h1);
            *(__nv_bfloat162*)&Bh[kr*BST + nn + 2] = __nv_bfloat162(h2,h3);
            *(__nv_bfloat162*)&Bl[kr*BST + nn    ] = __nv_bfloat162(l0,l1);
            *(__nv_bfloat162*)&Bl[kr*BST + nn + 2] = __nv_bfloat162(l2,l3);
        }
    };

    loadA(0); loadB(0);

    for (int c = 0; c < nk; c++) {
        storeAB();
        __syncthreads();
        if (c + 1 < nk) { loadA(c + 1); loadB(c + 1); }  // overlap with MMA

        #pragma unroll
        for (int pass = 0; pass < 3; pass++) {
            uint32_t abase = (pass == 1) ? al_base : ah_base;
            uint32_t bbase = (pass == 2) ? bl_base : bh_base;
            #pragma unroll
            for (int ks = 0; ks < 32; ks += 16) {
                uint32_t af[MT][4];
                #pragma unroll
                for (int mt = 0; mt < MT; mt++) {
                    uint32_t addr = abase +
                        (uint32_t)(((a_row + mt*16) * AST + ks + a_col) * 2);
                    ldsm4(af[mt][0], af[mt][1], af[mt][2], af[mt][3], addr);
                }
                uint32_t bfr[4][2];
                #pragma unroll
                for (int nt16 = 0; nt16 < 2; nt16++) {
                    uint32_t addr = bbase +
                        (uint32_t)(((ks + b_row) * BST + b_col + nt16*16) * 2);
                    ldsm4t(bfr[nt16*2][0], bfr[nt16*2][1],
                           bfr[nt16*2+1][0], bfr[nt16*2+1][1], addr);
                }
                #pragma unroll
                for (int mt = 0; mt < MT; mt++)
                    #pragma unroll
                    for (int nt = 0; nt < 4; nt++)
                        mma16816(acc[mt][nt], af[mt], bfr[nt]);
            }
        }
        __syncthreads();
    }

    int er = lane >> 2;
    int ec = (lane & 3) * 2;
    #pragma unroll
    for (int mt = 0; mt < MT; mt++) {
        #pragma unroll
        for (int nt = 0; nt < 4; nt++) {
            int row = m0 + wm + mt*16 + er;
            int col = n0 + wn + nt*8 + ec;
            *(float2*)(C + (size_t)row * Nd + col) =
                make_float2(acc[mt][nt][0], acc[mt][nt][1]);
            *(float2*)(C + (size_t)(row + 8) * Nd + col) =
                make_float2(acc[mt][nt][2], acc[mt][nt][3]);
        }
    }
}

// ---------------- z row stats (warp per edge row of 128) ----------------
__global__ __launch_bounds__(256) void k_zstats(const float* __restrict__ z) {
    int row  = blockIdx.x * 8 + (threadIdx.x >> 5);
    int lane = threadIdx.x & 31;
    float4 v = *(const float4*)(z + (size_t)row * CZ + lane * 4);
    float s  = v.x + v.y + v.z + v.w;
    float ss = v.x*v.x + v.y*v.y + v.z*v.z + v.w*v.w;
    #pragma unroll
    for (int o = 16; o; o >>= 1) {
        s  += __shfl_xor_sync(0xffffffffu, s,  o);
        ss += __shfl_xor_sync(0xffffffffu, ss, o);
    }
    if (lane == 0) {
        float mean = s * (1.0f / CZ);
        float var  = ss * (1.0f / CZ) - mean * mean;
        g_zstat[row*2    ] = mean;
        g_zstat[row*2 + 1] = rsqrtf(var + 1e-5f);
    }
}

// ---------------- z GEMM with LN fused into A-load ----------------
extern __shared__ float dynsm[];
__global__ __launch_bounds__(256) void k_zgemm(const float* __restrict__ z,
                                               const float* __restrict__ zsc,
                                               const float* __restrict__ zbi) {
    float* As = dynsm;                 // [128][129]
    float* Ws = dynsm + 128 * 129;     // [128][44]
    int tid = threadIdx.x;
    int r0  = blockIdx.x * 128;

    for (int i = tid; i < CZ * EOC; i += 256) Ws[i] = g_wz[i];
    #pragma unroll
    for (int t = 0; t < 16; t++) {
        int flat = (tid + t * 256) * 4;
        int row  = flat >> 7;
        int col  = flat & 127;
        float mean = g_zstat[(size_t)(r0 + row) * 2];
        float rstd = g_zstat[(size_t)(r0 + row) * 2 + 1];
        float4 v = *(const float4*)(z + (size_t)(r0 + row) * CZ + col);
        As[row*129 + col + 0] = (v.x - mean) * rstd * zsc[col + 0] + zbi[col + 0];
        As[row*129 + col + 1] = (v.y - mean) * rstd * zsc[col + 1] + zbi[col + 1];
        As[row*129 + col + 2] = (v.z - mean) * rstd * zsc[col + 2] + zbi[col + 2];
        As[row*129 + col + 3] = (v.w - mean) * rstd * zsc[col + 3] + zbi[col + 3];
    }
    __syncthreads();

    int rA = tid >> 2;
    int rB = rA + 64;
    int c0 = (tid & 3) * 11;
    float acc0[11], acc1[11];
    #pragma unroll
    for (int j = 0; j < 11; j++) { acc0[j] = 0.f; acc1[j] = 0.f; }
    #pragma unroll 8
    for (int kk = 0; kk < CZ; kk++) {
        float a0 = As[rA*129 + kk];
        float a1 = As[rB*129 + kk];
        #pragma unroll
        for (int j = 0; j < 11; j++) {
            float w = Ws[kk*EOC + c0 + j];
            acc0[j] += a0 * w;
            acc1[j] += a1 * w;
        }
    }
    #pragma unroll
    for (int j = 0; j < 11; j++) {
        g_eo[(size_t)(r0 + rA) * EOC + c0 + j] = acc0[j];
        g_eo[(size_t)(r0 + rB) * EOC + c0 + j] = acc1[j];
    }
}

// ---------------- attention: one block (128 thr) per node ----------------
// rot/trans cancel algebraically. Phase-1 neighbor data staged through smem
// with coalesced loads (kills 32-line gather wavefronts at L1tex).
#define KST 337   // smem row stride (floats): 192 k + 144 kpts, odd -> no conflicts

__global__ __launch_bounds__(128) void k_attn(const int*   __restrict__ edge_index,
                                              const float* __restrict__ s_mask,
                                              const float* __restrict__ head_w) {
    float* kv_sh = dynsm;              // [KNB][KST]: [0..191]=k, [192+h*12+r]=k_pts
    int node = blockIdx.x;
    int tid  = threadIdx.x;
    int b    = node >> 10;

    __shared__ int   nbroff_sh[KNB];
    __shared__ float msk_sh[KNB];
    __shared__ float q_sh[HH * CH];
    __shared__ float qp_sh[HH * PQn * 3];
    __shared__ float a_sh[HH][KNB];
    __shared__ float opt_sh[HH * PVn * 3];
    __shared__ float hw_sh[HH];
    __shared__ float b_sh[HH][KNB];

    if (tid < KNB) {
        int idx = edge_index[(size_t)node * KNB + tid];
        nbroff_sh[tid] = (b * NN + idx) * PROJ;
        msk_sh[tid]    = s_mask[node] * s_mask[b * NN + idx];
    }
    if (tid < HH)
        hw_sh[tid] = log1pf(__expf(head_w[tid])) * 0.13608276348795434f;
    __syncthreads();

    // ---- stage neighbor k-vectors (coalesced: same-row contiguous)
    for (int idx = tid; idx < KNB * 192; idx += 128) {
        int k = idx / 192, c = idx - k * 192;
        kv_sh[k * KST + c] = g_proj[nbroff_sh[k] + 192 + c];
    }
    // ---- stage neighbor k_pts (12 per head, strided source)
    for (int idx = tid; idx < KNB * 144; idx += 128) {
        int k = idx / 144, j = idx - k * 144;
        int h = j / 12, r = j - h * 12;
        kv_sh[k * KST + 192 + j] = g_proj[nbroff_sh[k] + 720 + h * 36 + r];
    }
    // ---- stage bias (b_sh[h][k])
    for (int idx = tid; idx < KNB * HH; idx += 128) {
        int k = idx / HH, h = idx - k * HH;
        b_sh[h][k] = g_eo[(size_t)(node * KNB + k) * EOC + h];
    }
    // ---- own q / q_pts (coalesced)
    for (int i = tid; i < HH * CH; i += 128)
        q_sh[i] = g_proj[(size_t)node * PROJ + i];
    for (int i = tid; i < HH * PQn * 3; i += 128)
        qp_sh[i] = g_proj[(size_t)node * PROJ + 576 + i];
    __syncthreads();

    int lane = tid & 31, warp = tid >> 5;
    float mk = msk_sh[lane];
    const float* kr = kv_sh + lane * KST;

    #pragma unroll
    for (int hi = 0; hi < 3; hi++) {
        int h = warp * 3 + hi;
        float dot = 0.f;
        #pragma unroll
        for (int c = 0; c < 16; c++)
            dot += q_sh[h * CH + c] * kr[h * CH + c];
        float sq = 0.f;
        #pragma unroll
        for (int j = 0; j < 12; j++) {
            float d = qp_sh[h * 12 + j] - kr[192 + h * 12 + j];
            sq += d * d;
        }
        float logit = dot * 0.14433756729740643f
                    + b_sh[h][lane] * 0.5773502691896258f
                    - 0.5f * hw_sh[h] * sq
                    + 100000.0f * (mk - 1.0f);
        float mx = logit;
        #pragma unroll
        for (int o = 16; o; o >>= 1) mx = fmaxf(mx, __shfl_xor_sync(0xffffffffu, mx, o));
        float e = __expf(logit - mx);
        float sm = e;
        #pragma unroll
        for (int o = 16; o; o >>= 1) sm += __shfl_xor_sync(0xffffffffu, sm, o);
        a_sh[h][lane] = e / sm;
    }
    __syncthreads();

    float* cv = g_cvec + (size_t)node * CVC;
    for (int oi = tid; oi < CVC; oi += 128) {
        float acc = 0.f;
        if (oi < 192) {
            int h = oi >> 4;
            int off = 384 + oi;
            #pragma unroll 8
            for (int k = 0; k < KNB; k++)
                acc += a_sh[h][k] * g_proj[nbroff_sh[k] + off];
            cv[oi] = acc;
        } else if (oi < 480) {
            int j = oi - 192;
            int h = j / 24, r = j % 24;
            int off = 720 + h * 36 + 12 + r;
            #pragma unroll 8
            for (int k = 0; k < KNB; k++)
                acc += a_sh[h][k] * g_proj[nbroff_sh[k] + off];
            opt_sh[j] = acc;
            cv[oi] = acc;
        } else if (oi >= 576) {
            int j = oi - 576;
            int h = j >> 5, c = j & 31;
            const float* eb = g_eo + (size_t)(node * KNB) * EOC + 12 + c;
            #pragma unroll 8
            for (int k = 0; k < KNB; k++)
                acc += a_sh[h][k] * eb[(size_t)k * EOC];
            cv[oi] = acc;
        }
    }
    __syncthreads();
    if (tid < HH * PVn) {
        float x = opt_sh[tid*3], y = opt_sh[tid*3+1], zz = opt_sh[tid*3+2];
        cv[480 + tid] = sqrtf(x*x + y*y + zz*zz + 1e-8f);
    }
}

// ---------------- launch ----------------
extern "C" void kernel_launch(void* const* d_in, const int* in_sizes, int n_in,
                              void* d_out, int out_size) {
    const float* s           = (const float*)d_in[0];
    const float* z           = (const float*)d_in[1];
    const int*   edge_index  = (const int*)  d_in[2];
    // d_in[3] rot, d_in[4] trans: cancel algebraically -> unused
    const float* s_mask      = (const float*)d_in[5];
    const float* ln_s_scale  = (const float*)d_in[6];
    const float* ln_s_bias   = (const float*)d_in[7];
    const float* ln_z_scale  = (const float*)d_in[8];
    const float* ln_z_bias   = (const float*)d_in[9];
    const float* w_q         = (const float*)d_in[10];
    const float* w_k         = (const float*)d_in[11];
    const float* w_v         = (const float*)d_in[12];
    const float* w_q_pts     = (const float*)d_in[13];
    const float* w_kv_pts    = (const float*)d_in[14];
    const float* w_b         = (const float*)d_in[15];
    const float* w_down_z    = (const float*)d_in[16];
    const float* head_weights= (const float*)d_in[17];
    const float* w_out       = (const float*)d_in[18];
    float* out = (float*)d_out;

    cudaFuncSetAttribute(k_zgemm, cudaFuncAttributeMaxDynamicSharedMemorySize, 92160);

    void *p_wcat, *p_proj, *p_stat, *p_cvec;
    cudaGetSymbolAddress(&p_wcat, g_wcat);
    cudaGetSymbolAddress(&p_proj, g_proj);
    cudaGetSymbolAddress(&p_stat, g_stat);
    cudaGetSymbolAddress(&p_cvec, g_cvec);

    pack_wcat<<<(CS * PROJ + 255) / 256, 256>>>(w_q, w_k, w_v, w_q_pts, w_kv_pts);
    pack_wz  <<<(CZ * EOC  + 255) / 256, 256>>>(w_b, w_down_z);
    k_stat_s <<<NODES / 8, 256>>>(s);

    // GEMM1: LN(s) @ wcat -> proj   (4096x384)@(384x1152)
    tgemm<128, true><<<dim3(NODES/128, PROJ/128), 256>>>(
        s, (const float*)p_wcat, (float*)p_proj, CS, PROJ, CS/32,
        (const float*)p_stat, ln_s_scale, ln_s_bias);

    // z path
    k_zstats<<<EDGES / 8, 256>>>(z);
    k_zgemm <<<EDGES / 128, 256, (128 * 129 + CZ * EOC) * sizeof(float)>>>(
        z, ln_z_scale, ln_z_bias);

    k_attn<<<NODES, 128, KNB * KST * sizeof(float)>>>(
        edge_index, s_mask, head_weights);

    // GEMM2: cvec @ w_out -> out    (4096x960)@(960x384), 64x128 tiles
    tgemm<64, false><<<dim3(NODES/64, COUT/128), 256>>>(
        (const float*)p_cvec, w_out, out, CVC, COUT, CVC/32,
        nullptr, nullptr, nullptr);
}

// round 7
// speedup vs baseline: 1.2998x; 1.2998x over previous
#include <cuda_runtime.h>
#include <cuda_bf16.h>
#include <math.h>
#include <stdint.h>

// ---------------- problem constants ----------------
#define BB   4
#define NN   1024
#define KNB  32
#define CS   384
#define CZ   128
#define CH   16
#define HH   12
#define PQn  4
#define PVn  8
#define NODES (BB*NN)        // 4096
#define PROJ  1152           // q(192)+k(192)+v(192)+qpts(144)+kvpts(432)
#define EDGES (NODES*KNB)    // 131072
#define EOC   44             // b_bias(12) + pair(32)
#define CVC   960            // o(192)+o_pt(288)+dists(96)+o_pair(384)
#define COUT  384
#define ZST   132            // z smem row stride (float4-aligned!)

// ---------------- scratch (device globals; no allocation) ----------------
__device__ float g_wcat[CS*PROJ];
__device__ float g_proj[NODES*PROJ];
__device__ float g_stat[NODES*2];
__device__ float g_wz  [CZ*EOC];
__device__ float g_eo  [EDGES*EOC];
__device__ float g_cvec[NODES*CVC];

// ---------------- helpers ----------------
__device__ __forceinline__ uint32_t smem_u32(const void* p) {
    uint32_t a;
    asm("{ .reg .u64 t; cvta.to.shared.u64 t, %1; cvt.u32.u64 %0, t; }"
        : "=r"(a) : "l"(p));
    return a;
}
__device__ __forceinline__ void cvt_hilo(float x, __nv_bfloat16& h, __nv_bfloat16& l) {
    h = __float2bfloat16(x);
    l = __float2bfloat16(x - __bfloat162float(h));
}
__device__ __forceinline__ void ldsm4(uint32_t& r0, uint32_t& r1, uint32_t& r2,
                                      uint32_t& r3, uint32_t addr) {
    asm volatile("ldmatrix.sync.aligned.m8n8.x4.shared.b16 {%0,%1,%2,%3}, [%4];"
                 : "=r"(r0), "=r"(r1), "=r"(r2), "=r"(r3) : "r"(addr));
}
__device__ __forceinline__ void ldsm4t(uint32_t& r0, uint32_t& r1, uint32_t& r2,
                                       uint32_t& r3, uint32_t addr) {
    asm volatile("ldmatrix.sync.aligned.m8n8.x4.trans.shared.b16 {%0,%1,%2,%3}, [%4];"
                 : "=r"(r0), "=r"(r1), "=r"(r2), "=r"(r3) : "r"(addr));
}
__device__ __forceinline__ void mma16816(float* c, const uint32_t* a, const uint32_t* b) {
    asm volatile(
        "mma.sync.aligned.m16n8k16.row.col.f32.bf16.bf16.f32 "
        "{%0,%1,%2,%3}, {%4,%5,%6,%7}, {%8,%9}, {%0,%1,%2,%3};"
        : "+f"(c[0]), "+f"(c[1]), "+f"(c[2]), "+f"(c[3])
        : "r"(a[0]), "r"(a[1]), "r"(a[2]), "r"(a[3]), "r"(b[0]), "r"(b[1]));
}

// ================= weight packing ==========================
__global__ void pack_wcat(const float* __restrict__ wq, const float* __restrict__ wk,
                          const float* __restrict__ wv, const float* __restrict__ wqp,
                          const float* __restrict__ wkv) {
    int idx = blockIdx.x * 256 + threadIdx.x;
    if (idx >= CS * PROJ) return;
    int i = idx / PROJ, j = idx % PROJ;
    float v;
    if      (j < 192) v = wq [i*192 + j];
    else if (j < 384) v = wk [i*192 + j - 192];
    else if (j < 576) v = wv [i*192 + j - 384];
    else if (j < 720) v = wqp[i*144 + j - 576];
    else              v = wkv[i*432 + j - 720];
    g_wcat[idx] = v;
}

__global__ void pack_wz(const float* __restrict__ wb, const float* __restrict__ wdz) {
    int idx = blockIdx.x * 256 + threadIdx.x;
    if (idx >= CZ * EOC) return;
    int i = idx / EOC, j = idx % EOC;
    g_wz[idx] = (j < 12) ? wb[i*12 + j] : wdz[i*32 + j - 12];
}

// ---------------- s row stats (warp per node) ----------------
__global__ __launch_bounds__(256) void k_stat_s(const float* __restrict__ s) {
    int node = blockIdx.x * 8 + (threadIdx.x >> 5);
    int lane = threadIdx.x & 31;
    const float* x = s + (size_t)node * CS;
    float sum = 0.f, ssq = 0.f;
    #pragma unroll
    for (int i = 0; i < 3; i++) {
        float4 v = *(const float4*)(x + lane * 4 + i * 128);
        sum += v.x + v.y + v.z + v.w;
        ssq += v.x*v.x + v.y*v.y + v.z*v.z + v.w*v.w;
    }
    #pragma unroll
    for (int o = 16; o; o >>= 1) {
        sum += __shfl_xor_sync(0xffffffffu, sum, o);
        ssq += __shfl_xor_sync(0xffffffffu, ssq, o);
    }
    if (lane == 0) {
        float mean = sum * (1.0f / CS);
        float var  = ssq * (1.0f / CS) - mean * mean;
        g_stat[node*2    ] = mean;
        g_stat[node*2 + 1] = rsqrtf(var + 1e-5f);
    }
}

// ================= bf16x3 tensor-core GEMM via mma.sync ====================
#define AST 40
#define BST 136

template<int BM, bool LN>
__global__ __launch_bounds__(256) void tgemm(const float* __restrict__ A,
                                             const float* __restrict__ B,
                                             float* __restrict__ C,
                                             int Kd, int Nd, int nk,
                                             const float* __restrict__ stat,
                                             const float* __restrict__ gam,
                                             const float* __restrict__ bet) {
    constexpr int MT  = BM / 32;
    constexpr int AL4 = BM / 32;
    __shared__ __nv_bfloat16 Ah[BM * AST];
    __shared__ __nv_bfloat16 Al[BM * AST];
    __shared__ __nv_bfloat16 Bh[32 * BST];
    __shared__ __nv_bfloat16 Bl[32 * BST];

    int tid = threadIdx.x, wid = tid >> 5, lane = tid & 31;
    int m0 = blockIdx.x * BM, n0 = blockIdx.y * 128;
    int wm = (wid >> 2) * (BM / 2);
    int wn = (wid & 3) * 32;

    float acc[MT][4][4];
    #pragma unroll
    for (int i = 0; i < MT; i++)
        #pragma unroll
        for (int j = 0; j < 4; j++)
            #pragma unroll
            for (int r = 0; r < 4; r++) acc[i][j][r] = 0.f;

    uint32_t ah_base = smem_u32(Ah), al_base = smem_u32(Al);
    uint32_t bh_base = smem_u32(Bh), bl_base = smem_u32(Bl);

    int a_row = wm + (lane & 15);
    int a_col = (lane >> 4) << 3;
    int b_row = (lane & 7) + ((lane >> 3) & 1) * 8;
    int b_col = wn + ((lane >> 4) << 3);

    float4 ar[AL4], br[4];

    auto loadA = [&](int c) {
        int k0 = c * 32;
        #pragma unroll
        for (int t = 0; t < AL4; t++) {
            int f4 = tid + t * 256;
            int row = f4 >> 3, col = (f4 & 7) * 4;
            float4 v = *(const float4*)(A + (size_t)(m0 + row) * Kd + k0 + col);
            if (LN) {
                float mean = stat[(m0 + row) * 2];
                float rstd = stat[(m0 + row) * 2 + 1];
                v.x = (v.x - mean) * rstd * __ldg(gam + k0 + col + 0) + __ldg(bet + k0 + col + 0);
                v.y = (v.y - mean) * rstd * __ldg(gam + k0 + col + 1) + __ldg(bet + k0 + col + 1);
                v.z = (v.z - mean) * rstd * __ldg(gam + k0 + col + 2) + __ldg(bet + k0 + col + 2);
                v.w = (v.w - mean) * rstd * __ldg(gam + k0 + col + 3) + __ldg(bet + k0 + col + 3);
            }
            ar[t] = v;
        }
    };
    auto loadB = [&](int c) {
        int k0 = c * 32;
        #pragma unroll
        for (int t = 0; t < 4; t++) {
            int f4 = tid + t * 256;
            int kr = f4 >> 5, nn = (f4 & 31) * 4;
            br[t] = *(const float4*)(B + (size_t)(k0 + kr) * Nd + n0 + nn);
        }
    };
    auto storeAB = [&]() {
        #pragma unroll
        for (int t = 0; t < AL4; t++) {
            int f4 = tid + t * 256;
            int row = f4 >> 3, col = (f4 & 7) * 4;
            __nv_bfloat16 h0,h1,h2,h3,l0,l1,l2,l3;
            cvt_hilo(ar[t].x,h0,l0); cvt_hilo(ar[t].y,h1,l1);
            cvt_hilo(ar[t].z,h2,l2); cvt_hilo(ar[t].w,h3,l3);
            *(__nv_bfloat162*)&Ah[row*AST + col    ] = __nv_bfloat162(h0,h1);
            *(__nv_bfloat162*)&Ah[row*AST + col + 2] = __nv_bfloat162(h2,h3);
            *(__nv_bfloat162*)&Al[row*AST + col    ] = __nv_bfloat162(l0,l1);
            *(__nv_bfloat162*)&Al[row*AST + col + 2] = __nv_bfloat162(l2,l3);
        }
        #pragma unroll
        for (int t = 0; t < 4; t++) {
            int f4 = tid + t * 256;
            int kr = f4 >> 5, nn = (f4 & 31) * 4;
            __nv_bfloat16 h0,h1,h2,h3,l0,l1,l2,l3;
            cvt_hilo(br[t].x,h0,l0); cvt_hilo(br[t].y,h1,l1);
            cvt_hilo(br[t].z,h2,l2); cvt_hilo(br[t].w,h3,l3);
            *(__nv_bfloat162*)&Bh[kr*BST + nn    ] = __nv_bfloat162(h0,h1);
            *(__nv_bfloat162*)&Bh[kr*BST + nn + 2] = __nv_bfloat162(h2,h3);
            *(__nv_bfloat162*)&Bl[kr*BST + nn    ] = __nv_bfloat162(l0,l1);
            *(__nv_bfloat162*)&Bl[kr*BST + nn + 2] = __nv_bfloat162(l2,l3);
        }
    };

    loadA(0); loadB(0);

    for (int c = 0; c < nk; c++) {
        storeAB();
        __syncthreads();
        if (c + 1 < nk) { loadA(c + 1); loadB(c + 1); }

        #pragma unroll
        for (int pass = 0; pass < 3; pass++) {
            uint32_t abase = (pass == 1) ? al_base : ah_base;
            uint32_t bbase = (pass == 2) ? bl_base : bh_base;
            #pragma unroll
            for (int ks = 0; ks < 32; ks += 16) {
                uint32_t af[MT][4];
                #pragma unroll
                for (int mt = 0; mt < MT; mt++) {
                    uint32_t addr = abase +
                        (uint32_t)(((a_row + mt*16) * AST + ks + a_col) * 2);
                    ldsm4(af[mt][0], af[mt][1], af[mt][2], af[mt][3], addr);
                }
                uint32_t bfr[4][2];
                #pragma unroll
                for (int nt16 = 0; nt16 < 2; nt16++) {
                    uint32_t addr = bbase +
                        (uint32_t)(((ks + b_row) * BST + b_col + nt16*16) * 2);
                    ldsm4t(bfr[nt16*2][0], bfr[nt16*2][1],
                           bfr[nt16*2+1][0], bfr[nt16*2+1][1], addr);
                }
                #pragma unroll
                for (int mt = 0; mt < MT; mt++)
                    #pragma unroll
                    for (int nt = 0; nt < 4; nt++)
                        mma16816(acc[mt][nt], af[mt], bfr[nt]);
            }
        }
        __syncthreads();
    }

    int er = lane >> 2;
    int ec = (lane & 3) * 2;
    #pragma unroll
    for (int mt = 0; mt < MT; mt++) {
        #pragma unroll
        for (int nt = 0; nt < 4; nt++) {
            int row = m0 + wm + mt*16 + er;
            int col = n0 + wn + nt*8 + ec;
            *(float2*)(C + (size_t)row * Nd + col) =
                make_float2(acc[mt][nt][0], acc[mt][nt][1]);
            *(float2*)(C + (size_t)(row + 8) * Nd + col) =
                make_float2(acc[mt][nt][2], acc[mt][nt][3]);
        }
    }
}

// ---------------- z GEMM: stats + LN fused, single z read ----------------
extern __shared__ float dynsm[];
__global__ __launch_bounds__(256) void k_zgemm(const float* __restrict__ z,
                                               const float* __restrict__ zsc,
                                               const float* __restrict__ zbi) {
    float* As      = dynsm;                  // [128][ZST] (ZST=132, float4-aligned)
    float* Ws      = dynsm + 128 * ZST;      // [128][44]
    float* mean_sh = Ws + 128 * EOC;         // [128]
    float* rstd_sh = mean_sh + 128;          // [128]
    int tid = threadIdx.x;
    int r0  = blockIdx.x * 128;

    for (int i = tid; i < CZ * EOC; i += 256) Ws[i] = g_wz[i];
    // raw tile (float4 ok: row*ZST is multiple of 4)
    #pragma unroll
    for (int t = 0; t < 16; t++) {
        int flat = (tid + t * 256) * 4;
        int row  = flat >> 7;
        int col  = flat & 127;
        *(float4*)&As[row*ZST + col] =
            *(const float4*)(z + (size_t)(r0 + row) * CZ + col);
    }
    __syncthreads();
    // per-row stats: warp w handles rows w*16..w*16+15
    {
        int w = tid >> 5, lane = tid & 31;
        for (int rr = 0; rr < 16; rr++) {
            int row = w * 16 + rr;
            float s1 = 0.f, s2 = 0.f;
            #pragma unroll
            for (int c = 0; c < 4; c++) {
                float v = As[row*ZST + lane + c * 32];
                s1 += v; s2 += v * v;
            }
            #pragma unroll
            for (int o = 16; o; o >>= 1) {
                s1 += __shfl_xor_sync(0xffffffffu, s1, o);
                s2 += __shfl_xor_sync(0xffffffffu, s2, o);
            }
            if (lane == 0) {
                float mean = s1 * (1.0f / CZ);
                float var  = s2 * (1.0f / CZ) - mean * mean;
                mean_sh[row] = mean;
                rstd_sh[row] = rsqrtf(var + 1e-5f);
            }
        }
    }
    __syncthreads();
    // apply LN in place
    #pragma unroll
    for (int t = 0; t < 16; t++) {
        int flat = (tid + t * 256) * 4;
        int row  = flat >> 7;
        int col  = flat & 127;
        float mean = mean_sh[row], rstd = rstd_sh[row];
        float4 v = *(float4*)&As[row*ZST + col];
        v.x = (v.x - mean) * rstd * __ldg(zsc + col + 0) + __ldg(zbi + col + 0);
        v.y = (v.y - mean) * rstd * __ldg(zsc + col + 1) + __ldg(zbi + col + 1);
        v.z = (v.z - mean) * rstd * __ldg(zsc + col + 2) + __ldg(zbi + col + 2);
        v.w = (v.w - mean) * rstd * __ldg(zsc + col + 3) + __ldg(zbi + col + 3);
        *(float4*)&As[row*ZST + col] = v;
    }
    __syncthreads();

    int rA = tid >> 2;
    int rB = rA + 64;
    int c0 = (tid & 3) * 11;
    float acc0[11], acc1[11];
    #pragma unroll
    for (int j = 0; j < 11; j++) { acc0[j] = 0.f; acc1[j] = 0.f; }
    #pragma unroll 8
    for (int kk = 0; kk < CZ; kk++) {
        float a0 = As[rA*ZST + kk];
        float a1 = As[rB*ZST + kk];
        #pragma unroll
        for (int j = 0; j < 11; j++) {
            float w = Ws[kk*EOC + c0 + j];
            acc0[j] += a0 * w;
            acc1[j] += a1 * w;
        }
    }
    #pragma unroll
    for (int j = 0; j < 11; j++) {
        g_eo[(size_t)(r0 + rA) * EOC + c0 + j] = acc0[j];
        g_eo[(size_t)(r0 + rB) * EOC + c0 + j] = acc1[j];
    }
}

// ---------------- attention: one block (256 thr) per node ----------------
// rot/trans cancel algebraically. Phase-1 neighbor data staged via smem
// (coalesced); 256 threads keep 32 warps/SM resident for phase-2 latency.
#define KST 337   // smem row stride (floats): 192 k + 144 kpts

__global__ __launch_bounds__(256) void k_attn(const int*   __restrict__ edge_index,
                                              const float* __restrict__ s_mask,
                                              const float* __restrict__ head_w) {
    float* kv_sh = dynsm;              // [KNB][KST]
    int node = blockIdx.x;
    int tid  = threadIdx.x;
    int b    = node >> 10;

    __shared__ int   nbroff_sh[KNB];
    __shared__ float msk_sh[KNB];
    __shared__ float q_sh[HH * CH];
    __shared__ float qp_sh[HH * PQn * 3];
    __shared__ float a_sh[HH][KNB];
    __shared__ float opt_sh[HH * PVn * 3];
    __shared__ float hw_sh[HH];
    __shared__ float b_sh[HH][KNB];

    if (tid < KNB) {
        int idx = edge_index[(size_t)node * KNB + tid];
        nbroff_sh[tid] = (b * NN + idx) * PROJ;
        msk_sh[tid]    = s_mask[node] * s_mask[b * NN + idx];
    }
    if (tid < HH)
        hw_sh[tid] = log1pf(__expf(head_w[tid])) * 0.13608276348795434f;
    __syncthreads();

    // stage neighbor k-vectors (row-contiguous source -> coalesced)
    for (int idx = tid; idx < KNB * 192; idx += 256) {
        int k = idx / 192, c = idx - k * 192;
        kv_sh[k * KST + c] = g_proj[nbroff_sh[k] + 192 + c];
    }
    // stage neighbor k_pts (12 per head)
    for (int idx = tid; idx < KNB * 144; idx += 256) {
        int k = idx / 144, j = idx - k * 144;
        int h = j / 12, r = j - h * 12;
        kv_sh[k * KST + 192 + j] = g_proj[nbroff_sh[k] + 720 + h * 36 + r];
    }
    // stage bias
    for (int idx = tid; idx < KNB * HH; idx += 256) {
        int k = idx / HH, h = idx - k * HH;
        b_sh[h][k] = g_eo[(size_t)(node * KNB + k) * EOC + h];
    }
    // own q / q_pts
    for (int i = tid; i < HH * CH; i += 256)
        q_sh[i] = g_proj[(size_t)node * PROJ + i];
    for (int i = tid; i < HH * PQn * 3; i += 256)
        qp_sh[i] = g_proj[(size_t)node * PROJ + 576 + i];
    __syncthreads();

    int lane = tid & 31, warp = tid >> 5;
    float mk = msk_sh[lane];
    const float* kr = kv_sh + lane * KST;

    // heads: warp w -> h=w; warps 0..3 also h=8+w
    #pragma unroll
    for (int rep = 0; rep < 2; rep++) {
        if (rep == 1 && warp >= 4) break;
        int h = (rep == 0) ? warp : 8 + warp;
        float dot = 0.f;
        #pragma unroll
        for (int c = 0; c < 16; c++)
            dot += q_sh[h * CH + c] * kr[h * CH + c];
        float sq = 0.f;
        #pragma unroll
        for (int j = 0; j < 12; j++) {
            float d = qp_sh[h * 12 + j] - kr[192 + h * 12 + j];
            sq += d * d;
        }
        float logit = dot * 0.14433756729740643f
                    + b_sh[h][lane] * 0.5773502691896258f
                    - 0.5f * hw_sh[h] * sq
                    + 100000.0f * (mk - 1.0f);
        float mx = logit;
        #pragma unroll
        for (int o = 16; o; o >>= 1) mx = fmaxf(mx, __shfl_xor_sync(0xffffffffu, mx, o));
        float e = __expf(logit - mx);
        float sm = e;
        #pragma unroll
        for (int o = 16; o; o >>= 1) sm += __shfl_xor_sync(0xffffffffu, sm, o);
        a_sh[h][lane] = e / sm;
    }
    __syncthreads();

    float* cv = g_cvec + (size_t)node * CVC;
    for (int oi = tid; oi < CVC; oi += 256) {
        float acc = 0.f;
        if (oi < 192) {
            int h = oi >> 4;
            int off = 384 + oi;
            #pragma unroll 8
            for (int k = 0; k < KNB; k++)
                acc += a_sh[h][k] * g_proj[nbroff_sh[k] + off];
            cv[oi] = acc;
        } else if (oi < 480) {
            int j = oi - 192;
            int h = j / 24, r = j % 24;
            int off = 720 + h * 36 + 12 + r;
            #pragma unroll 8
            for (int k = 0; k < KNB; k++)
                acc += a_sh[h][k] * g_proj[nbroff_sh[k] + off];
            opt_sh[j] = acc;
            cv[oi] = acc;
        } else if (oi >= 576) {
            int j = oi - 576;
            int h = j >> 5, c = j & 31;
            const float* eb = g_eo + (size_t)(node * KNB) * EOC + 12 + c;
            #pragma unroll 8
            for (int k = 0; k < KNB; k++)
                acc += a_sh[h][k] * eb[(size_t)k * EOC];
            cv[oi] = acc;
        }
    }
    __syncthreads();
    if (tid < HH * PVn) {
        float x = opt_sh[tid*3], y = opt_sh[tid*3+1], zz = opt_sh[tid*3+2];
        cv[480 + tid] = sqrtf(x*x + y*y + zz*zz + 1e-8f);
    }
}

// ---------------- launch ----------------
extern "C" void kernel_launch(void* const* d_in, const int* in_sizes, int n_in,
                              void* d_out, int out_size) {
    const float* s           = (const float*)d_in[0];
    const float* z           = (const float*)d_in[1];
    const int*   edge_index  = (const int*)  d_in[2];
    // d_in[3] rot, d_in[4] trans: cancel algebraically -> unused
    const float* s_mask      = (const float*)d_in[5];
    const float* ln_s_scale  = (const float*)d_in[6];
    const float* ln_s_bias   = (const float*)d_in[7];
    const float* ln_z_scale  = (const float*)d_in[8];
    const float* ln_z_bias   = (const float*)d_in[9];
    const float* w_q         = (const float*)d_in[10];
    const float* w_k         = (const float*)d_in[11];
    const float* w_v         = (const float*)d_in[12];
    const float* w_q_pts     = (const float*)d_in[13];
    const float* w_kv_pts    = (const float*)d_in[14];
    const float* w_b         = (const float*)d_in[15];
    const float* w_down_z    = (const float*)d_in[16];
    const float* head_weights= (const float*)d_in[17];
    const float* w_out       = (const float*)d_in[18];
    float* out = (float*)d_out;

    const int zsmem = (128 * ZST + 128 * EOC + 256) * sizeof(float);
    cudaFuncSetAttribute(k_zgemm, cudaFuncAttributeMaxDynamicSharedMemorySize, zsmem);

    void *p_wcat, *p_proj, *p_stat, *p_cvec;
    cudaGetSymbolAddress(&p_wcat, g_wcat);
    cudaGetSymbolAddress(&p_proj, g_proj);
    cudaGetSymbolAddress(&p_stat, g_stat);
    cudaGetSymbolAddress(&p_cvec, g_cvec);

    pack_wcat<<<(CS * PROJ + 255) / 256, 256>>>(w_q, w_k, w_v, w_q_pts, w_kv_pts);
    pack_wz  <<<(CZ * EOC  + 255) / 256, 256>>>(w_b, w_down_z);
    k_stat_s <<<NODES / 8, 256>>>(s);

    // GEMM1: LN(s) @ wcat -> proj   (4096x384)@(384x1152)
    tgemm<128, true><<<dim3(NODES/128, PROJ/128), 256>>>(
        s, (const float*)p_wcat, (float*)p_proj, CS, PROJ, CS/32,
        (const float*)p_stat, ln_s_scale, ln_s_bias);

    // z path (stats + LN + GEMM in one kernel, single z read)
    k_zgemm<<<EDGES / 128, 256, zsmem>>>(z, ln_z_scale, ln_z_bias);

    k_attn<<<NODES, 256, KNB * KST * sizeof(float)>>>(
        edge_index, s_mask, head_weights);

    // GEMM2: cvec @ w_out -> out    (4096x960)@(960x384)
    tgemm<128, false><<<dim3(NODES/128, COUT/128), 256>>>(
        (const float*)p_cvec, w_out, out, CVC, COUT, CVC/32,
        nullptr, nullptr, nullptr);
}